// round 1
// baseline (speedup 1.0000x reference)
#include <cuda_runtime.h>
#include <math.h>

#define NN 100000
#define NE 1600000
#define NG 1000

// ---- scratch (static device globals; no allocation) ----
__device__ __align__(16) float g_posg[NN * 2];
__device__ __align__(16) float g_ncs [NN * 2];
__device__ __align__(16) float g_nacc[NN * 4];   // deg,sumdist,sumC,sumS -> later [0]=invdeg
__device__ __align__(16) float g_gacc[NG * 4];   // sumx,sumy,cnt,0
__device__ __align__(16) float g_demb[(size_t)NE * 16];
__device__ __align__(16) float g_xs  [NN * 16];
__device__ __align__(16) float g_xrot[NN * 32];  // [rep][2] interleaved
__device__ __align__(16) float g_y   [NN * 32];  // Wmix @ x_rot
__device__ __align__(16) float g_as  [NN * 16];  // x_s @ Ws1_top
__device__ __align__(16) float g_gate[NN * 16];
__device__ __align__(16) float g_aggR[NN * 32];
__device__ __align__(16) float g_aggS[NN * 16];

__device__ __forceinline__ void red4(float* a, float x, float y, float z, float w) {
    asm volatile("red.global.add.v4.f32 [%0], {%1,%2,%3,%4};"
                 :: "l"(a), "f"(x), "f"(y), "f"(z), "f"(w) : "memory");
}
__device__ __forceinline__ float lrelu(float x) { return x > 0.f ? x : 0.01f * x; }

// ---- zero accumulators + output ----
__global__ void kZero(float* out) {
    int i = blockIdx.x * blockDim.x + threadIdx.x;
    for (int t = i; t < NN * 4; t += gridDim.x * blockDim.x) g_nacc[t] = 0.f;
    if (i < NG * 4) g_gacc[i] = 0.f;
    if (i < NG * 6) out[i] = 0.f;
}

// ---- per-graph mean accumulation ----
__global__ void kGraphAcc(const float* __restrict__ pos, const int* __restrict__ batch) {
    int n = blockIdx.x * blockDim.x + threadIdx.x;
    if (n >= NN) return;
    int b = batch[n];
    red4(&g_gacc[b * 4], pos[2 * n], pos[2 * n + 1], 1.f, 0.f);
}

// ---- center positions + node rotation (cos,sin) ----
__global__ void kCenter(const float* __restrict__ pos, const int* __restrict__ batch) {
    int n = blockIdx.x * blockDim.x + threadIdx.x;
    if (n >= NN) return;
    int b = batch[n];
    float4 ga = *(const float4*)&g_gacc[b * 4];
    float inv = 1.f / fmaxf(ga.z, 1.f);
    float px = pos[2 * n]     - ga.x * inv;
    float py = pos[2 * n + 1] - ga.y * inv;
    g_posg[2 * n] = px; g_posg[2 * n + 1] = py;
    float r2 = px * px + py * py;
    float c = 1.f, s = 0.f;
    if (r2 > 0.f) { float ir = rsqrtf(r2); c = px * ir; s = py * ir; }
    g_ncs[2 * n] = c; g_ncs[2 * n + 1] = s;
}

// ---- per-edge: dist, bessel embedding, scatter (1, dist, cos, sin) to row ----
__global__ void kEdge(const int* __restrict__ ei) {
    int e = blockIdx.x * blockDim.x + threadIdx.x;
    if (e >= NE) return;
    int r = ei[e], c = ei[NE + e];
    float vx = g_posg[2 * r] - g_posg[2 * c];
    float vy = g_posg[2 * r + 1] - g_posg[2 * c + 1];
    float r2 = vx * vx + vy * vy;
    float d = 0.f, cc = 1.f, ss = 0.f;
    if (r2 > 0.f) { float ir = rsqrtf(r2); d = r2 * ir; cc = vx * ir; ss = vy * ir; }
    float invd = 1.41421356237f / (d + 1e-8f);
    float emb[16];
    const float PI_F = 3.14159265358979f;
#pragma unroll
    for (int k = 0; k < 16; k++)
        emb[k] = sinf(((float)(k + 1) * PI_F) * d) * invd;
    float4* dp = (float4*)&g_demb[(size_t)e * 16];
    dp[0] = make_float4(emb[0], emb[1], emb[2], emb[3]);
    dp[1] = make_float4(emb[4], emb[5], emb[6], emb[7]);
    dp[2] = make_float4(emb[8], emb[9], emb[10], emb[11]);
    dp[3] = make_float4(emb[12], emb[13], emb[14], emb[15]);
    red4(&g_nacc[r * 4], 1.f, d, cc, ss);
}

// ---- per-node init: x_s embedding + x_rot = M_n w_j ----
__global__ void kNodeInit(const float* __restrict__ wse, const float* __restrict__ bse,
                          const float* __restrict__ Wemb) {
    int n = blockIdx.x * blockDim.x + threadIdx.x;
    if (n >= NN) return;
    float4 a = *(const float4*)&g_nacc[n * 4];
    float deg = fmaxf(a.x, 1.f);
    float invdeg = 1.f / deg;
    float dmean = a.y * invdeg;
    float Cm = a.z * invdeg, Sm = a.w * invdeg;
#pragma unroll
    for (int i = 0; i < 16; i++)
        g_xs[n * 16 + i] = lrelu(dmean * wse[i] + bse[i]);
#pragma unroll
    for (int j = 0; j < 16; j++) {
        float w0 = Wemb[2 * j], w1 = Wemb[2 * j + 1];
        g_xrot[n * 32 + 2 * j]     = Cm * w0 - Sm * w1;
        g_xrot[n * 32 + 2 * j + 1] = Sm * w0 + Cm * w1;
    }
    g_nacc[n * 4] = invdeg;  // stash for layers
}

// ---- per-node pre-layer: y = Wmix@x_rot, a_s = x_s@Ws1_top, gate; zero agg ----
__global__ void kNodePre(const float* __restrict__ Wmix, const float* __restrict__ Wgate,
                         const float* __restrict__ bgate, const float* __restrict__ Ws1,
                         int layer) {
    __shared__ __align__(16) float sMix[256], sGate[256], sWs[256], sbg[16];
    for (int t = threadIdx.x; t < 256; t += blockDim.x) {
        sMix[t]  = Wmix [layer * 256 + t];
        sGate[t] = Wgate[layer * 256 + t];
        sWs[t]   = Ws1  [layer * 512 + t];   // rows 0..15
    }
    if (threadIdx.x < 16) sbg[threadIdx.x] = bgate[layer * 16 + threadIdx.x];
    __syncthreads();
    int n = blockIdx.x * blockDim.x + threadIdx.x;
    if (n >= NN) return;
    float xs[16], xr[32];
    {
        const float4* p = (const float4*)&g_xs[n * 16];
#pragma unroll
        for (int q = 0; q < 4; q++) { float4 v = p[q]; xs[4*q]=v.x; xs[4*q+1]=v.y; xs[4*q+2]=v.z; xs[4*q+3]=v.w; }
        const float4* pr = (const float4*)&g_xrot[n * 32];
#pragma unroll
        for (int q = 0; q < 8; q++) { float4 v = pr[q]; xr[4*q]=v.x; xr[4*q+1]=v.y; xr[4*q+2]=v.z; xr[4*q+3]=v.w; }
    }
    float* yo = &g_y[n * 32];
#pragma unroll
    for (int i = 0; i < 16; i++) {
        float ax = 0.f, ay = 0.f;
#pragma unroll
        for (int j = 0; j < 16; j++) {
            float w = sMix[i * 16 + j];
            ax = fmaf(w, xr[2 * j], ax);
            ay = fmaf(w, xr[2 * j + 1], ay);
        }
        yo[2 * i] = ax; yo[2 * i + 1] = ay;
    }
    float gt[16], as_[16];
#pragma unroll
    for (int i = 0; i < 16; i++) { gt[i] = sbg[i]; as_[i] = 0.f; }
#pragma unroll
    for (int k = 0; k < 16; k++) {
        float xv = xs[k];
#pragma unroll
        for (int i = 0; i < 16; i++) {
            gt[i]  = fmaf(xv, sGate[k * 16 + i], gt[i]);
            as_[i] = fmaf(xv, sWs[k * 16 + i], as_[i]);
        }
    }
#pragma unroll
    for (int i = 0; i < 16; i++) {
        g_gate[n * 16 + i] = 1.f / (1.f + expf(-gt[i]));
        g_as[n * 16 + i] = as_[i];
    }
    float4 z = make_float4(0.f, 0.f, 0.f, 0.f);
    float4* ar = (float4*)&g_aggR[n * 32];
#pragma unroll
    for (int q = 0; q < 8; q++) ar[q] = z;
    float4* as4 = (float4*)&g_aggS[n * 16];
#pragma unroll
    for (int q = 0; q < 4; q++) as4[q] = z;
}

// ---- per-edge layer (hot): g, bs from demb; gather y/a_s at col; scatter to row ----
__global__ void kEdgeLayer(const int* __restrict__ ei,
                           const float* __restrict__ Wg, const float* __restrict__ bg,
                           const float* __restrict__ Ws1, const float* __restrict__ bs1,
                           int layer) {
    __shared__ __align__(16) float sWg[256], sWs[256], sb[32];
    for (int t = threadIdx.x; t < 256; t += blockDim.x) {
        sWg[t] = Wg[layer * 256 + t];
        sWs[t] = Ws1[layer * 512 + 256 + t];  // rows 16..31
    }
    if (threadIdx.x < 16) sb[threadIdx.x] = bg[layer * 16 + threadIdx.x];
    else if (threadIdx.x < 32) sb[threadIdx.x] = bs1[layer * 16 + threadIdx.x - 16];
    __syncthreads();
    int e = blockIdx.x * blockDim.x + threadIdx.x;
    if (e >= NE) return;
    int r = ei[e], c = ei[NE + e];
    float emb[16];
    {
        const float4* dp = (const float4*)&g_demb[(size_t)e * 16];
#pragma unroll
        for (int q = 0; q < 4; q++) { float4 v = dp[q]; emb[4*q]=v.x; emb[4*q+1]=v.y; emb[4*q+2]=v.z; emb[4*q+3]=v.w; }
    }
    float g[16], bs[16];
#pragma unroll
    for (int i = 0; i < 16; i++) { g[i] = sb[i]; bs[i] = sb[16 + i]; }
#pragma unroll
    for (int k = 0; k < 16; k++) {
        float dv = emb[k];
#pragma unroll
        for (int i = 0; i < 16; i++) {
            g[i]  = fmaf(dv, sWg[k * 16 + i], g[i]);
            bs[i] = fmaf(dv, sWs[k * 16 + i], bs[i]);
        }
    }
    const float4* yp = (const float4*)&g_y[(size_t)c * 32];
    float* aggR = &g_aggR[(size_t)r * 32];
#pragma unroll
    for (int q = 0; q < 8; q++) {
        float4 y4 = yp[q];
        int i0 = 2 * q;
        red4(&aggR[q * 4], g[i0] * y4.x, g[i0] * y4.y, g[i0 + 1] * y4.z, g[i0 + 1] * y4.w);
    }
    const float4* ap = (const float4*)&g_as[(size_t)c * 16];
    float* aggS = &g_aggS[(size_t)r * 16];
#pragma unroll
    for (int q = 0; q < 4; q++) {
        float4 a4 = ap[q];
        red4(&aggS[q * 4],
             lrelu(a4.x + bs[q * 4]), lrelu(a4.y + bs[q * 4 + 1]),
             lrelu(a4.z + bs[q * 4 + 2]), lrelu(a4.w + bs[q * 4 + 3]));
    }
}

// ---- per-node post-layer: apply gate and degree normalization ----
__global__ void kNodePost(int layer) {
    int n = blockIdx.x * blockDim.x + threadIdx.x;
    if (n >= NN) return;
    float invd = g_nacc[n * 4];
#pragma unroll
    for (int j = 0; j < 16; j++) {
        float gt = g_gate[n * 16 + j] * invd;
        g_xrot[n * 32 + 2 * j]     += gt * g_aggR[n * 32 + 2 * j];
        g_xrot[n * 32 + 2 * j + 1] += gt * g_aggR[n * 32 + 2 * j + 1];
    }
#pragma unroll
    for (int i = 0; i < 16; i++)
        g_xs[n * 16 + i] += g_aggS[n * 16 + i] * invd;
}

// ---- readout: rotate out, 48->144->6 MLP, scatter to graphs ----
__global__ void kOut(const float* __restrict__ W1, const float* __restrict__ b1,
                     const float* __restrict__ W2, const float* __restrict__ b2,
                     const int* __restrict__ batch, float* __restrict__ out) {
    __shared__ __align__(16) float sW1[48 * 144];
    __shared__ __align__(16) float sW2[144 * 6];
    __shared__ __align__(16) float sb1[144];
    __shared__ float sb2[6];
    for (int t = threadIdx.x; t < 48 * 144; t += blockDim.x) sW1[t] = W1[t];
    for (int t = threadIdx.x; t < 144 * 6; t += blockDim.x) sW2[t] = W2[t];
    for (int t = threadIdx.x; t < 144; t += blockDim.x) sb1[t] = b1[t];
    if (threadIdx.x < 6) sb2[threadIdx.x] = b2[threadIdx.x];
    __syncthreads();
    int n = blockIdx.x * blockDim.x + threadIdx.x;
    if (n >= NN) return;
    float xc[48];
    {
        const float4* p = (const float4*)&g_xs[n * 16];
#pragma unroll
        for (int q = 0; q < 4; q++) { float4 v = p[q]; xc[4*q]=v.x; xc[4*q+1]=v.y; xc[4*q+2]=v.z; xc[4*q+3]=v.w; }
    }
    float cc = g_ncs[2 * n], ss = g_ncs[2 * n + 1];
#pragma unroll
    for (int j = 0; j < 16; j++) {
        float x0 = g_xrot[n * 32 + 2 * j], x1 = g_xrot[n * 32 + 2 * j + 1];
        xc[16 + 2 * j]     = cc * x0 - ss * x1;
        xc[16 + 2 * j + 1] = ss * x0 + cc * x1;
    }
    float u[6];
#pragma unroll
    for (int q = 0; q < 6; q++) u[q] = sb2[q];
    for (int o = 0; o < 144; o += 4) {
        float4 h = *(const float4*)&sb1[o];
#pragma unroll
        for (int k = 0; k < 48; k++) {
            float4 w = *(const float4*)&sW1[k * 144 + o];
            float xv = xc[k];
            h.x = fmaf(xv, w.x, h.x);
            h.y = fmaf(xv, w.y, h.y);
            h.z = fmaf(xv, w.z, h.z);
            h.w = fmaf(xv, w.w, h.w);
        }
        h.x = lrelu(h.x); h.y = lrelu(h.y); h.z = lrelu(h.z); h.w = lrelu(h.w);
        float hv[4] = {h.x, h.y, h.z, h.w};
#pragma unroll
        for (int j = 0; j < 4; j++)
#pragma unroll
            for (int q = 0; q < 6; q++)
                u[q] = fmaf(hv[j], sW2[(o + j) * 6 + q], u[q]);
    }
    int b = batch[n];
#pragma unroll
    for (int q = 0; q < 6; q++) atomicAdd(&out[b * 6 + q], u[q]);
}

extern "C" void kernel_launch(void* const* d_in, const int* in_sizes, int n_in,
                              void* d_out, int out_size) {
    const float* pos   = (const float*)d_in[0];
    const float* Wemb  = (const float*)d_in[1];
    const float* wse   = (const float*)d_in[2];
    const float* bse   = (const float*)d_in[3];
    const float* Wg    = (const float*)d_in[4];
    const float* bg    = (const float*)d_in[5];
    const float* Wmix  = (const float*)d_in[6];
    const float* Wgate = (const float*)d_in[7];
    const float* bgate = (const float*)d_in[8];
    const float* Ws1   = (const float*)d_in[9];
    const float* bs1   = (const float*)d_in[10];
    const float* W1    = (const float*)d_in[11];
    const float* b1    = (const float*)d_in[12];
    const float* W2    = (const float*)d_in[13];
    const float* b2    = (const float*)d_in[14];
    const int*   ei    = (const int*)d_in[15];
    const int*   batch = (const int*)d_in[16];
    float* out = (float*)d_out;

    int nb = (NN + 255) / 256;
    int eb = (NE + 255) / 256;

    kZero<<<1563, 256>>>(out);
    kGraphAcc<<<nb, 256>>>(pos, batch);
    kCenter<<<nb, 256>>>(pos, batch);
    kEdge<<<eb, 256>>>(ei);
    kNodeInit<<<nb, 256>>>(wse, bse, Wemb);
    for (int l = 0; l < 3; l++) {
        kNodePre<<<nb, 256>>>(Wmix, Wgate, bgate, Ws1, l);
        kEdgeLayer<<<eb, 256>>>(ei, Wg, bg, Ws1, bs1, l);
        kNodePost<<<nb, 256>>>(l);
    }
    kOut<<<(NN + 127) / 128, 128>>>(W1, b1, W2, b2, batch, out);
}

// round 2
// speedup vs baseline: 1.3374x; 1.3374x over previous
#include <cuda_runtime.h>
#include <math.h>

#define NN 100000
#define NE 1600000
#define NG 1000
typedef unsigned long long ull;

// ---- scratch (static device globals; no allocation) ----
__device__ __align__(16) float g_posg[NN * 2];
__device__ __align__(16) float g_ncs [NN * 2];
__device__ __align__(16) float g_nacc[NN * 4];   // deg,sumdist,sumC,sumS -> later [0]=invdeg
__device__ __align__(16) float g_gacc[NG * 4];   // sumx,sumy,cnt,0
__device__ __align__(16) float g_epk [(size_t)NE * 4]; // s1=sin(pi d), c1=cos(pi d), invd=sqrt2/(d+eps), d
__device__ __align__(16) float g_xs  [NN * 16];
__device__ __align__(16) float g_xrot[NN * 32];  // [rep][2] interleaved
__device__ __align__(16) float g_y   [NN * 32];  // Wmix @ x_rot
__device__ __align__(16) float g_as  [NN * 16];  // x_s @ Ws1_top
__device__ __align__(16) float g_gate[NN * 16];
__device__ __align__(16) float g_aggR[NN * 32];
__device__ __align__(16) float g_aggS[NN * 16];

__device__ __forceinline__ void red4(float* a, float x, float y, float z, float w) {
    asm volatile("red.global.add.v4.f32 [%0], {%1,%2,%3,%4};"
                 :: "l"(a), "f"(x), "f"(y), "f"(z), "f"(w));
}
__device__ __forceinline__ float lrelu(float x) { return x > 0.f ? x : 0.01f * x; }
__device__ __forceinline__ ull fma2(ull a, ull b, ull c) {
    ull d; asm("fma.rn.f32x2 %0,%1,%2,%3;" : "=l"(d) : "l"(a), "l"(b), "l"(c)); return d;
}
__device__ __forceinline__ ull pk2(float x, float y) {
    ull r; asm("mov.b64 %0,{%1,%2};" : "=l"(r) : "f"(x), "f"(y)); return r;
}
__device__ __forceinline__ float2 upk(ull v) {
    float2 r; asm("mov.b64 {%0,%1},%2;" : "=f"(r.x), "=f"(r.y) : "l"(v)); return r;
}

// ---- zero accumulators + output ----
__global__ void kZero(float* out) {
    int i = blockIdx.x * blockDim.x + threadIdx.x;
    for (int t = i; t < NN * 4; t += gridDim.x * blockDim.x) g_nacc[t] = 0.f;
    if (i < NG * 4) g_gacc[i] = 0.f;
    if (i < NG * 6) out[i] = 0.f;
}

__global__ void kGraphAcc(const float* __restrict__ pos, const int* __restrict__ batch) {
    int n = blockIdx.x * blockDim.x + threadIdx.x;
    if (n >= NN) return;
    int b = batch[n];
    red4(&g_gacc[b * 4], pos[2 * n], pos[2 * n + 1], 1.f, 0.f);
}

__global__ void kCenter(const float* __restrict__ pos, const int* __restrict__ batch) {
    int n = blockIdx.x * blockDim.x + threadIdx.x;
    if (n >= NN) return;
    int b = batch[n];
    float4 ga = *(const float4*)&g_gacc[b * 4];
    float inv = 1.f / fmaxf(ga.z, 1.f);
    float px = pos[2 * n]     - ga.x * inv;
    float py = pos[2 * n + 1] - ga.y * inv;
    g_posg[2 * n] = px; g_posg[2 * n + 1] = py;
    float r2 = px * px + py * py;
    float c = 1.f, s = 0.f;
    if (r2 > 0.f) { float ir = rsqrtf(r2); c = px * ir; s = py * ir; }
    g_ncs[2 * n] = c; g_ncs[2 * n + 1] = s;
}

// ---- per-edge: dist, pack (sin pi d, cos pi d, invd, d), scatter (1,d,cos,sin) to row ----
__global__ void kEdge(const int* __restrict__ ei) {
    int e = blockIdx.x * blockDim.x + threadIdx.x;
    if (e >= NE) return;
    int r = ei[e], c = ei[NE + e];
    float vx = g_posg[2 * r] - g_posg[2 * c];
    float vy = g_posg[2 * r + 1] - g_posg[2 * c + 1];
    float r2 = vx * vx + vy * vy;
    float d = 0.f, cc = 1.f, ss = 0.f;
    if (r2 > 0.f) { float ir = rsqrtf(r2); d = r2 * ir; cc = vx * ir; ss = vy * ir; }
    float invd = 1.41421356237f / (d + 1e-8f);
    float s1, c1;
    sincosf(3.14159265358979f * d, &s1, &c1);
    *(float4*)&g_epk[(size_t)e * 4] = make_float4(s1, c1, invd, d);
    red4(&g_nacc[r * 4], 1.f, d, cc, ss);
}

// ---- fused node kernel: (post of layer-1 if layer>0, init if layer==0) + pre of layer ----
__global__ void kNodeFuse(const float* __restrict__ wse, const float* __restrict__ bse,
                          const float* __restrict__ Wemb,
                          const float* __restrict__ Wmix, const float* __restrict__ Wgate,
                          const float* __restrict__ bgate, const float* __restrict__ Ws1,
                          int layer) {
    __shared__ __align__(16) float sMix[256];
    __shared__ ull sGate2[128], sWs2[128], sbg2[8];
    for (int t = threadIdx.x; t < 256; t += blockDim.x) sMix[t] = Wmix[layer * 256 + t];
    for (int t = threadIdx.x; t < 128; t += blockDim.x) {
        sGate2[t] = ((const ull*)(Wgate + layer * 256))[t];
        sWs2[t]   = ((const ull*)(Ws1 + layer * 512))[t];    // rows 0..15
    }
    if (threadIdx.x < 8) sbg2[threadIdx.x] = ((const ull*)(bgate + layer * 16))[threadIdx.x];
    __syncthreads();
    int n = blockIdx.x * blockDim.x + threadIdx.x;
    if (n >= NN) return;

    float xs[16], xr[32];
    if (layer == 0) {
        float4 a = *(const float4*)&g_nacc[n * 4];
        float deg = fmaxf(a.x, 1.f);
        float invdeg = 1.f / deg;
        float dmean = a.y * invdeg;
        float Cm = a.z * invdeg, Sm = a.w * invdeg;
#pragma unroll
        for (int i = 0; i < 16; i++) xs[i] = lrelu(dmean * wse[i] + bse[i]);
#pragma unroll
        for (int j = 0; j < 16; j++) {
            float w0 = Wemb[2 * j], w1 = Wemb[2 * j + 1];
            xr[2 * j]     = Cm * w0 - Sm * w1;
            xr[2 * j + 1] = Sm * w0 + Cm * w1;
        }
        g_nacc[n * 4] = invdeg;
        // store state
        float4* po = (float4*)&g_xs[n * 16];
#pragma unroll
        for (int q = 0; q < 4; q++) po[q] = make_float4(xs[4*q], xs[4*q+1], xs[4*q+2], xs[4*q+3]);
        float4* pr = (float4*)&g_xrot[n * 32];
#pragma unroll
        for (int q = 0; q < 8; q++) pr[q] = make_float4(xr[4*q], xr[4*q+1], xr[4*q+2], xr[4*q+3]);
    } else {
        const float4* p = (const float4*)&g_xs[n * 16];
#pragma unroll
        for (int q = 0; q < 4; q++) { float4 v = p[q]; xs[4*q]=v.x; xs[4*q+1]=v.y; xs[4*q+2]=v.z; xs[4*q+3]=v.w; }
        const float4* pr = (const float4*)&g_xrot[n * 32];
#pragma unroll
        for (int q = 0; q < 8; q++) { float4 v = pr[q]; xr[4*q]=v.x; xr[4*q+1]=v.y; xr[4*q+2]=v.z; xr[4*q+3]=v.w; }
        float invd = g_nacc[n * 4];
#pragma unroll
        for (int j = 0; j < 16; j++) {
            float gt = g_gate[n * 16 + j] * invd;
            xr[2 * j]     += gt * g_aggR[n * 32 + 2 * j];
            xr[2 * j + 1] += gt * g_aggR[n * 32 + 2 * j + 1];
        }
#pragma unroll
        for (int i = 0; i < 16; i++) xs[i] += g_aggS[n * 16 + i] * invd;
        float4* po = (float4*)&g_xs[n * 16];
#pragma unroll
        for (int q = 0; q < 4; q++) po[q] = make_float4(xs[4*q], xs[4*q+1], xs[4*q+2], xs[4*q+3]);
        float4* pw = (float4*)&g_xrot[n * 32];
#pragma unroll
        for (int q = 0; q < 8; q++) pw[q] = make_float4(xr[4*q], xr[4*q+1], xr[4*q+2], xr[4*q+3]);
    }

    // y = Wmix @ x_rot
    float* yo = &g_y[n * 32];
#pragma unroll
    for (int i = 0; i < 16; i++) {
        float ax = 0.f, ay = 0.f;
#pragma unroll
        for (int j = 0; j < 16; j++) {
            float w = sMix[i * 16 + j];
            ax = fmaf(w, xr[2 * j], ax);
            ay = fmaf(w, xr[2 * j + 1], ay);
        }
        yo[2 * i] = ax; yo[2 * i + 1] = ay;
    }
    // gate + a_s via f32x2
    ull gt2[8], as2[8];
#pragma unroll
    for (int i = 0; i < 8; i++) { gt2[i] = sbg2[i]; as2[i] = 0ull; }
#pragma unroll
    for (int k = 0; k < 16; k++) {
        ull xv2 = pk2(xs[k], xs[k]);
#pragma unroll
        for (int i = 0; i < 8; i++) {
            gt2[i] = fma2(xv2, sGate2[k * 8 + i], gt2[i]);
            as2[i] = fma2(xv2, sWs2[k * 8 + i], as2[i]);
        }
    }
#pragma unroll
    for (int i = 0; i < 8; i++) {
        float2 gv = upk(gt2[i]);
        g_gate[n * 16 + 2 * i]     = 1.f / (1.f + expf(-gv.x));
        g_gate[n * 16 + 2 * i + 1] = 1.f / (1.f + expf(-gv.y));
        ((ull*)&g_as[n * 16])[i] = as2[i];
    }
    float4 z = make_float4(0.f, 0.f, 0.f, 0.f);
    float4* ar = (float4*)&g_aggR[n * 32];
#pragma unroll
    for (int q = 0; q < 8; q++) ar[q] = z;
    float4* as4 = (float4*)&g_aggS[n * 16];
#pragma unroll
    for (int q = 0; q < 4; q++) as4[q] = z;
}

// ---- per-edge layer (hot) ----
__global__ void __launch_bounds__(256) kEdgeLayer(const int* __restrict__ ei,
                           const float* __restrict__ Wg, const float* __restrict__ bg,
                           const float* __restrict__ Ws1, const float* __restrict__ bs1,
                           int layer) {
    __shared__ ull sWg2[128], sWs2[128], sbg2[8], sbs2[8];
    for (int t = threadIdx.x; t < 128; t += blockDim.x) {
        sWg2[t] = ((const ull*)(Wg + layer * 256))[t];
        sWs2[t] = ((const ull*)(Ws1 + layer * 512 + 256))[t];  // rows 16..31
    }
    if (threadIdx.x < 8) {
        sbg2[threadIdx.x] = ((const ull*)(bg + layer * 16))[threadIdx.x];
        sbs2[threadIdx.x] = ((const ull*)(bs1 + layer * 16))[threadIdx.x];
    }
    __syncthreads();
    int e = blockIdx.x * blockDim.x + threadIdx.x;
    if (e >= NE) return;
    int c = ei[NE + e];
    int r = ei[e];
    float4 ep = *(const float4*)&g_epk[(size_t)e * 4];
    // batch ALL gathers up front (L2 latency overlap)
    const float4* yp = (const float4*)&g_y[(size_t)c * 32];
    float4 y0 = yp[0], y1 = yp[1], y2 = yp[2], y3 = yp[3];
    float4 y4 = yp[4], y5 = yp[5], y6 = yp[6], y7 = yp[7];
    const float4* ap = (const float4*)&g_as[(size_t)c * 16];
    float4 a0 = ap[0], a1 = ap[1], a2 = ap[2], a3 = ap[3];

    // rebuild bessel embedding from (sin pi d, cos pi d) recurrence
    float s1 = ep.x, c1 = ep.y, invd = ep.z;
    float emb[16];
    emb[0] = s1 * invd;
    float sk = s1, ck = c1;
#pragma unroll
    for (int k = 1; k < 16; k++) {
        float sn = fmaf(sk, c1,  ck * s1);
        float cn = fmaf(ck, c1, -sk * s1);
        emb[k] = sn * invd;
        sk = sn; ck = cn;
    }
    // g = emb @ Wg + bg ; bs = emb @ Ws1_bot + bs1 (f32x2 packed)
    ull g2[8], b2[8];
#pragma unroll
    for (int i = 0; i < 8; i++) { g2[i] = sbg2[i]; b2[i] = sbs2[i]; }
#pragma unroll
    for (int k = 0; k < 16; k++) {
        ull dv2 = pk2(emb[k], emb[k]);
#pragma unroll
        for (int i = 0; i < 8; i++) {
            g2[i] = fma2(dv2, sWg2[k * 8 + i], g2[i]);
            b2[i] = fma2(dv2, sWs2[k * 8 + i], b2[i]);
        }
    }
    float* aggR = &g_aggR[(size_t)r * 32];
    {
        float2 gp;
        gp = upk(g2[0]); red4(aggR + 0,  gp.x * y0.x, gp.x * y0.y, gp.y * y0.z, gp.y * y0.w);
        gp = upk(g2[1]); red4(aggR + 4,  gp.x * y1.x, gp.x * y1.y, gp.y * y1.z, gp.y * y1.w);
        gp = upk(g2[2]); red4(aggR + 8,  gp.x * y2.x, gp.x * y2.y, gp.y * y2.z, gp.y * y2.w);
        gp = upk(g2[3]); red4(aggR + 12, gp.x * y3.x, gp.x * y3.y, gp.y * y3.z, gp.y * y3.w);
        gp = upk(g2[4]); red4(aggR + 16, gp.x * y4.x, gp.x * y4.y, gp.y * y4.z, gp.y * y4.w);
        gp = upk(g2[5]); red4(aggR + 20, gp.x * y5.x, gp.x * y5.y, gp.y * y5.z, gp.y * y5.w);
        gp = upk(g2[6]); red4(aggR + 24, gp.x * y6.x, gp.x * y6.y, gp.y * y6.z, gp.y * y6.w);
        gp = upk(g2[7]); red4(aggR + 28, gp.x * y7.x, gp.x * y7.y, gp.y * y7.z, gp.y * y7.w);
    }
    float* aggS = &g_aggS[(size_t)r * 16];
    {
        float2 u0 = upk(b2[0]), u1 = upk(b2[1]);
        red4(aggS + 0, lrelu(a0.x + u0.x), lrelu(a0.y + u0.y), lrelu(a0.z + u1.x), lrelu(a0.w + u1.y));
        u0 = upk(b2[2]); u1 = upk(b2[3]);
        red4(aggS + 4, lrelu(a1.x + u0.x), lrelu(a1.y + u0.y), lrelu(a1.z + u1.x), lrelu(a1.w + u1.y));
        u0 = upk(b2[4]); u1 = upk(b2[5]);
        red4(aggS + 8, lrelu(a2.x + u0.x), lrelu(a2.y + u0.y), lrelu(a2.z + u1.x), lrelu(a2.w + u1.y));
        u0 = upk(b2[6]); u1 = upk(b2[7]);
        red4(aggS + 12, lrelu(a3.x + u0.x), lrelu(a3.y + u0.y), lrelu(a3.z + u1.x), lrelu(a3.w + u1.y));
    }
}

// ---- readout: final post + rotate out + 48->144->6 MLP + graph scatter ----
__global__ void kOut(const float* __restrict__ W1, const float* __restrict__ b1,
                     const float* __restrict__ W2, const float* __restrict__ b2,
                     const int* __restrict__ batch, float* __restrict__ out) {
    __shared__ __align__(16) float sW1[48 * 144];
    __shared__ __align__(16) float sW2[144 * 6];
    __shared__ __align__(16) float sb1[144];
    __shared__ float sb2[6];
    for (int t = threadIdx.x; t < 48 * 144; t += blockDim.x) sW1[t] = W1[t];
    for (int t = threadIdx.x; t < 144 * 6; t += blockDim.x) sW2[t] = W2[t];
    for (int t = threadIdx.x; t < 144; t += blockDim.x) sb1[t] = b1[t];
    if (threadIdx.x < 6) sb2[threadIdx.x] = b2[threadIdx.x];
    __syncthreads();
    int n = blockIdx.x * blockDim.x + threadIdx.x;
    if (n >= NN) return;
    float invd = g_nacc[n * 4];
    float xc[48];
#pragma unroll
    for (int i = 0; i < 16; i++)
        xc[i] = g_xs[n * 16 + i] + g_aggS[n * 16 + i] * invd;
    float cc = g_ncs[2 * n], ss = g_ncs[2 * n + 1];
#pragma unroll
    for (int j = 0; j < 16; j++) {
        float gt = g_gate[n * 16 + j] * invd;
        float x0 = g_xrot[n * 32 + 2 * j]     + gt * g_aggR[n * 32 + 2 * j];
        float x1 = g_xrot[n * 32 + 2 * j + 1] + gt * g_aggR[n * 32 + 2 * j + 1];
        xc[16 + 2 * j]     = cc * x0 - ss * x1;
        xc[16 + 2 * j + 1] = ss * x0 + cc * x1;
    }
    float u[6];
#pragma unroll
    for (int q = 0; q < 6; q++) u[q] = sb2[q];
    for (int o = 0; o < 144; o += 4) {
        float4 h = *(const float4*)&sb1[o];
#pragma unroll
        for (int k = 0; k < 48; k++) {
            float4 w = *(const float4*)&sW1[k * 144 + o];
            float xv = xc[k];
            h.x = fmaf(xv, w.x, h.x);
            h.y = fmaf(xv, w.y, h.y);
            h.z = fmaf(xv, w.z, h.z);
            h.w = fmaf(xv, w.w, h.w);
        }
        h.x = lrelu(h.x); h.y = lrelu(h.y); h.z = lrelu(h.z); h.w = lrelu(h.w);
        float hv[4] = {h.x, h.y, h.z, h.w};
#pragma unroll
        for (int j = 0; j < 4; j++)
#pragma unroll
            for (int q = 0; q < 6; q++)
                u[q] = fmaf(hv[j], sW2[(o + j) * 6 + q], u[q]);
    }
    int b = batch[n];
#pragma unroll
    for (int q = 0; q < 6; q++) atomicAdd(&out[b * 6 + q], u[q]);
}

extern "C" void kernel_launch(void* const* d_in, const int* in_sizes, int n_in,
                              void* d_out, int out_size) {
    const float* pos   = (const float*)d_in[0];
    const float* Wemb  = (const float*)d_in[1];
    const float* wse   = (const float*)d_in[2];
    const float* bse   = (const float*)d_in[3];
    const float* Wg    = (const float*)d_in[4];
    const float* bg    = (const float*)d_in[5];
    const float* Wmix  = (const float*)d_in[6];
    const float* Wgate = (const float*)d_in[7];
    const float* bgate = (const float*)d_in[8];
    const float* Ws1   = (const float*)d_in[9];
    const float* bs1   = (const float*)d_in[10];
    const float* W1    = (const float*)d_in[11];
    const float* b1    = (const float*)d_in[12];
    const float* W2    = (const float*)d_in[13];
    const float* b2    = (const float*)d_in[14];
    const int*   ei    = (const int*)d_in[15];
    const int*   batch = (const int*)d_in[16];
    float* out = (float*)d_out;

    int nb = (NN + 255) / 256;
    int eb = (NE + 255) / 256;

    kZero<<<1563, 256>>>(out);
    kGraphAcc<<<nb, 256>>>(pos, batch);
    kCenter<<<nb, 256>>>(pos, batch);
    kEdge<<<eb, 256>>>(ei);
    for (int l = 0; l < 3; l++) {
        kNodeFuse<<<nb, 256>>>(wse, bse, Wemb, Wmix, Wgate, bgate, Ws1, l);
        kEdgeLayer<<<eb, 256>>>(ei, Wg, bg, Ws1, bs1, l);
    }
    kOut<<<(NN + 127) / 128, 128>>>(W1, b1, W2, b2, batch, out);
}

// round 3
// speedup vs baseline: 1.4078x; 1.0526x over previous
#include <cuda_runtime.h>
#include <math.h>

#define NN 100000
#define NE 1600000
#define NG 1000
#define NBLK 391   // ceil(NN/256)
typedef unsigned long long ull;

// ---- scratch (static device globals; no allocation) ----
__device__ __align__(16) float g_posg[NN * 2];
__device__ __align__(16) float g_ncs [NN * 2];
__device__ __align__(16) float g_nacc[NN * 4];   // deg,sumdist,sumC,sumS -> later [0]=invdeg
__device__ __align__(16) float g_gacc[NG * 4];   // sumx,sumy,cnt,0
__device__ int   g_deg[NN];
__device__ int   g_rowstart[NN];
__device__ int   g_cursor[NN];
__device__ int   g_psum[512];
__device__ __align__(16) float4 g_rec[NE];       // col(bits), sin(pi d), cos(pi d), invd
__device__ int   g_erow[NE];
__device__ __align__(16) float g_xs  [NN * 16];
__device__ __align__(16) float g_xrot[NN * 32];
__device__ __align__(16) float g_y   [NN * 32];
__device__ __align__(16) float g_as  [NN * 16];
__device__ __align__(16) float g_gate[NN * 16];
__device__ __align__(16) float g_aggR[NN * 32];
__device__ __align__(16) float g_aggS[NN * 16];

__device__ __forceinline__ void red4(float* a, float x, float y, float z, float w) {
    asm volatile("red.global.add.v4.f32 [%0], {%1,%2,%3,%4};"
                 :: "l"(a), "f"(x), "f"(y), "f"(z), "f"(w));
}
__device__ __forceinline__ float lrelu(float x) { return x > 0.f ? x : 0.01f * x; }
__device__ __forceinline__ ull fma2(ull a, ull b, ull c) {
    ull d; asm("fma.rn.f32x2 %0,%1,%2,%3;" : "=l"(d) : "l"(a), "l"(b), "l"(c)); return d;
}
__device__ __forceinline__ ull pk2(float x, float y) {
    ull r; asm("mov.b64 %0,{%1,%2};" : "=l"(r) : "f"(x), "f"(y)); return r;
}
__device__ __forceinline__ float2 upk(ull v) {
    float2 r; asm("mov.b64 {%0,%1},%2;" : "=f"(r.x), "=f"(r.y) : "l"(v)); return r;
}

// ---- zero ----
__global__ void kZero(float* out) {
    int i = blockIdx.x * blockDim.x + threadIdx.x;
    for (int t = i; t < NN * 4; t += gridDim.x * blockDim.x) g_nacc[t] = 0.f;
    for (int t = i; t < NN; t += gridDim.x * blockDim.x) g_deg[t] = 0;
    if (i < NG * 4) g_gacc[i] = 0.f;
    if (i < NG * 6) out[i] = 0.f;
}

__global__ void kGraphAcc(const float* __restrict__ pos, const int* __restrict__ batch) {
    int n = blockIdx.x * blockDim.x + threadIdx.x;
    if (n >= NN) return;
    red4(&g_gacc[batch[n] * 4], pos[2 * n], pos[2 * n + 1], 1.f, 0.f);
}

__global__ void kCenter(const float* __restrict__ pos, const int* __restrict__ batch) {
    int n = blockIdx.x * blockDim.x + threadIdx.x;
    if (n >= NN) return;
    float4 ga = *(const float4*)&g_gacc[batch[n] * 4];
    float inv = 1.f / fmaxf(ga.z, 1.f);
    float px = pos[2 * n]     - ga.x * inv;
    float py = pos[2 * n + 1] - ga.y * inv;
    g_posg[2 * n] = px; g_posg[2 * n + 1] = py;
    float r2 = px * px + py * py;
    float c = 1.f, s = 0.f;
    if (r2 > 0.f) { float ir = rsqrtf(r2); c = px * ir; s = py * ir; }
    g_ncs[2 * n] = c; g_ncs[2 * n + 1] = s;
}

// ---- CSR build ----
__global__ void kDeg(const int* __restrict__ ei) {
    int e = blockIdx.x * blockDim.x + threadIdx.x;
    if (e < NE) atomicAdd(&g_deg[ei[e]], 1);
}

__global__ void kScanA() {
    __shared__ int s[256];
    int n = blockIdx.x * 256 + threadIdx.x;
    int v = (n < NN) ? g_deg[n] : 0;
    s[threadIdx.x] = v; __syncthreads();
    for (int d = 1; d < 256; d <<= 1) {
        int t = (threadIdx.x >= d) ? s[threadIdx.x - d] : 0;
        __syncthreads();
        s[threadIdx.x] += t;
        __syncthreads();
    }
    if (n < NN) g_rowstart[n] = s[threadIdx.x] - v;  // local exclusive
    if (threadIdx.x == 255) g_psum[blockIdx.x] = s[255];
}

__global__ void kScanB() {
    __shared__ int s[512];
    int t = threadIdx.x;
    int v = (t < NBLK) ? g_psum[t] : 0;
    s[t] = v; __syncthreads();
    for (int d = 1; d < 512; d <<= 1) {
        int u = (t >= d) ? s[t - d] : 0;
        __syncthreads();
        s[t] += u;
        __syncthreads();
    }
    if (t < NBLK) g_psum[t] = s[t] - v;  // exclusive block offsets
}

__global__ void kScanC() {
    int n = blockIdx.x * 256 + threadIdx.x;
    if (n >= NN) return;
    int rs = g_rowstart[n] + g_psum[blockIdx.x];
    g_rowstart[n] = rs;
    g_cursor[n] = rs;
}

// ---- per-edge geometry + CSR fill ----
__global__ void kEdgeFill(const int* __restrict__ ei) {
    int e = blockIdx.x * blockDim.x + threadIdx.x;
    if (e >= NE) return;
    int r = ei[e], c = ei[NE + e];
    float vx = g_posg[2 * r] - g_posg[2 * c];
    float vy = g_posg[2 * r + 1] - g_posg[2 * c + 1];
    float r2 = vx * vx + vy * vy;
    float d = 0.f, cc = 1.f, ss = 0.f;
    if (r2 > 0.f) { float ir = rsqrtf(r2); d = r2 * ir; cc = vx * ir; ss = vy * ir; }
    float invd = 1.41421356237f / (d + 1e-8f);
    float s1, c1;
    sincosf(3.14159265358979f * d, &s1, &c1);
    int pos = atomicAdd(&g_cursor[r], 1);
    g_rec[pos] = make_float4(__int_as_float(c), s1, c1, invd);
    g_erow[pos] = r;
    red4(&g_nacc[r * 4], 1.f, d, cc, ss);
}

// ---- fused node kernel ----
__global__ void kNodeFuse(const float* __restrict__ wse, const float* __restrict__ bse,
                          const float* __restrict__ Wemb,
                          const float* __restrict__ Wmix, const float* __restrict__ Wgate,
                          const float* __restrict__ bgate, const float* __restrict__ Ws1,
                          int layer) {
    __shared__ __align__(16) float sMix[256];
    __shared__ ull sGate2[128], sWs2[128], sbg2[8];
    for (int t = threadIdx.x; t < 256; t += blockDim.x) sMix[t] = Wmix[layer * 256 + t];
    for (int t = threadIdx.x; t < 128; t += blockDim.x) {
        sGate2[t] = ((const ull*)(Wgate + layer * 256))[t];
        sWs2[t]   = ((const ull*)(Ws1 + layer * 512))[t];
    }
    if (threadIdx.x < 8) sbg2[threadIdx.x] = ((const ull*)(bgate + layer * 16))[threadIdx.x];
    __syncthreads();
    int n = blockIdx.x * blockDim.x + threadIdx.x;
    if (n >= NN) return;

    float xs[16], xr[32];
    if (layer == 0) {
        float4 a = *(const float4*)&g_nacc[n * 4];
        float deg = fmaxf(a.x, 1.f);
        float invdeg = 1.f / deg;
        float dmean = a.y * invdeg;
        float Cm = a.z * invdeg, Sm = a.w * invdeg;
#pragma unroll
        for (int i = 0; i < 16; i++) xs[i] = lrelu(dmean * wse[i] + bse[i]);
#pragma unroll
        for (int j = 0; j < 16; j++) {
            float w0 = Wemb[2 * j], w1 = Wemb[2 * j + 1];
            xr[2 * j]     = Cm * w0 - Sm * w1;
            xr[2 * j + 1] = Sm * w0 + Cm * w1;
        }
        g_nacc[n * 4] = invdeg;
        float4* po = (float4*)&g_xs[n * 16];
#pragma unroll
        for (int q = 0; q < 4; q++) po[q] = make_float4(xs[4*q], xs[4*q+1], xs[4*q+2], xs[4*q+3]);
        float4* pr = (float4*)&g_xrot[n * 32];
#pragma unroll
        for (int q = 0; q < 8; q++) pr[q] = make_float4(xr[4*q], xr[4*q+1], xr[4*q+2], xr[4*q+3]);
    } else {
        const float4* p = (const float4*)&g_xs[n * 16];
#pragma unroll
        for (int q = 0; q < 4; q++) { float4 v = p[q]; xs[4*q]=v.x; xs[4*q+1]=v.y; xs[4*q+2]=v.z; xs[4*q+3]=v.w; }
        const float4* pr = (const float4*)&g_xrot[n * 32];
#pragma unroll
        for (int q = 0; q < 8; q++) { float4 v = pr[q]; xr[4*q]=v.x; xr[4*q+1]=v.y; xr[4*q+2]=v.z; xr[4*q+3]=v.w; }
        float invd = g_nacc[n * 4];
#pragma unroll
        for (int j = 0; j < 16; j++) {
            float gt = g_gate[n * 16 + j] * invd;
            xr[2 * j]     += gt * g_aggR[n * 32 + 2 * j];
            xr[2 * j + 1] += gt * g_aggR[n * 32 + 2 * j + 1];
        }
#pragma unroll
        for (int i = 0; i < 16; i++) xs[i] += g_aggS[n * 16 + i] * invd;
        float4* po = (float4*)&g_xs[n * 16];
#pragma unroll
        for (int q = 0; q < 4; q++) po[q] = make_float4(xs[4*q], xs[4*q+1], xs[4*q+2], xs[4*q+3]);
        float4* pw = (float4*)&g_xrot[n * 32];
#pragma unroll
        for (int q = 0; q < 8; q++) pw[q] = make_float4(xr[4*q], xr[4*q+1], xr[4*q+2], xr[4*q+3]);
    }

    float* yo = &g_y[n * 32];
#pragma unroll
    for (int i = 0; i < 16; i++) {
        float ax = 0.f, ay = 0.f;
#pragma unroll
        for (int j = 0; j < 16; j++) {
            float w = sMix[i * 16 + j];
            ax = fmaf(w, xr[2 * j], ax);
            ay = fmaf(w, xr[2 * j + 1], ay);
        }
        yo[2 * i] = ax; yo[2 * i + 1] = ay;
    }
    ull gt2[8], as2[8];
#pragma unroll
    for (int i = 0; i < 8; i++) { gt2[i] = sbg2[i]; as2[i] = 0ull; }
#pragma unroll
    for (int k = 0; k < 16; k++) {
        ull xv2 = pk2(xs[k], xs[k]);
#pragma unroll
        for (int i = 0; i < 8; i++) {
            gt2[i] = fma2(xv2, sGate2[k * 8 + i], gt2[i]);
            as2[i] = fma2(xv2, sWs2[k * 8 + i], as2[i]);
        }
    }
#pragma unroll
    for (int i = 0; i < 8; i++) {
        float2 gv = upk(gt2[i]);
        g_gate[n * 16 + 2 * i]     = 1.f / (1.f + expf(-gv.x));
        g_gate[n * 16 + 2 * i + 1] = 1.f / (1.f + expf(-gv.y));
        ((ull*)&g_as[n * 16])[i] = as2[i];
    }
    float4 z = make_float4(0.f, 0.f, 0.f, 0.f);
    float4* ar = (float4*)&g_aggR[n * 32];
#pragma unroll
    for (int q = 0; q < 8; q++) ar[q] = z;
    float4* as4 = (float4*)&g_aggS[n * 16];
#pragma unroll
    for (int q = 0; q < 4; q++) as4[q] = z;
}

// ---- per-edge layer (hot): CSR order, warp segmented reduction ----
__global__ void __launch_bounds__(256) kEdgeLayer(
                           const float* __restrict__ Wg, const float* __restrict__ bg,
                           const float* __restrict__ Ws1, const float* __restrict__ bs1,
                           int layer) {
    __shared__ ull sWg2[128], sWs2[128], sbg2[8], sbs2[8];
    for (int t = threadIdx.x; t < 128; t += blockDim.x) {
        sWg2[t] = ((const ull*)(Wg + layer * 256))[t];
        sWs2[t] = ((const ull*)(Ws1 + layer * 512 + 256))[t];
    }
    if (threadIdx.x < 8) {
        sbg2[threadIdx.x] = ((const ull*)(bg + layer * 16))[threadIdx.x];
        sbs2[threadIdx.x] = ((const ull*)(bs1 + layer * 16))[threadIdx.x];
    }
    __syncthreads();
    int p = blockIdx.x * blockDim.x + threadIdx.x;   // NE divisible by 256
    int lane = threadIdx.x & 31;
    int r = g_erow[p];
    float4 rec = g_rec[p];
    int c = __float_as_int(rec.x);

    // batch gathers
    const float4* yp = (const float4*)&g_y[(size_t)c * 32];
    float4 y0 = yp[0], y1 = yp[1], y2 = yp[2], y3 = yp[3];
    float4 y4 = yp[4], y5 = yp[5], y6 = yp[6], y7 = yp[7];
    const float4* ap = (const float4*)&g_as[(size_t)c * 16];
    float4 a0 = ap[0], a1 = ap[1], a2 = ap[2], a3 = ap[3];

    // bessel from angle-addition recurrence
    float s1 = rec.y, c1 = rec.z, invd = rec.w;
    float emb[16];
    emb[0] = s1 * invd;
    float sk = s1, ck = c1;
#pragma unroll
    for (int k = 1; k < 16; k++) {
        float sn = fmaf(sk, c1,  ck * s1);
        float cn = fmaf(ck, c1, -sk * s1);
        emb[k] = sn * invd;
        sk = sn; ck = cn;
    }
    ull g2[8], b2[8];
#pragma unroll
    for (int i = 0; i < 8; i++) { g2[i] = sbg2[i]; b2[i] = sbs2[i]; }
#pragma unroll
    for (int k = 0; k < 16; k++) {
        ull dv2 = pk2(emb[k], emb[k]);
#pragma unroll
        for (int i = 0; i < 8; i++) {
            g2[i] = fma2(dv2, sWg2[k * 8 + i], g2[i]);
            b2[i] = fma2(dv2, sWs2[k * 8 + i], b2[i]);
        }
    }
    float m[48];
    {
        float2 gp;
        gp = upk(g2[0]); m[0]=gp.x*y0.x; m[1]=gp.x*y0.y; m[2]=gp.y*y0.z; m[3]=gp.y*y0.w;
        gp = upk(g2[1]); m[4]=gp.x*y1.x; m[5]=gp.x*y1.y; m[6]=gp.y*y1.z; m[7]=gp.y*y1.w;
        gp = upk(g2[2]); m[8]=gp.x*y2.x; m[9]=gp.x*y2.y; m[10]=gp.y*y2.z; m[11]=gp.y*y2.w;
        gp = upk(g2[3]); m[12]=gp.x*y3.x; m[13]=gp.x*y3.y; m[14]=gp.y*y3.z; m[15]=gp.y*y3.w;
        gp = upk(g2[4]); m[16]=gp.x*y4.x; m[17]=gp.x*y4.y; m[18]=gp.y*y4.z; m[19]=gp.y*y4.w;
        gp = upk(g2[5]); m[20]=gp.x*y5.x; m[21]=gp.x*y5.y; m[22]=gp.y*y5.z; m[23]=gp.y*y5.w;
        gp = upk(g2[6]); m[24]=gp.x*y6.x; m[25]=gp.x*y6.y; m[26]=gp.y*y6.z; m[27]=gp.y*y6.w;
        gp = upk(g2[7]); m[28]=gp.x*y7.x; m[29]=gp.x*y7.y; m[30]=gp.y*y7.z; m[31]=gp.y*y7.w;
        float2 u0, u1;
        u0 = upk(b2[0]); u1 = upk(b2[1]);
        m[32]=lrelu(a0.x+u0.x); m[33]=lrelu(a0.y+u0.y); m[34]=lrelu(a0.z+u1.x); m[35]=lrelu(a0.w+u1.y);
        u0 = upk(b2[2]); u1 = upk(b2[3]);
        m[36]=lrelu(a1.x+u0.x); m[37]=lrelu(a1.y+u0.y); m[38]=lrelu(a1.z+u1.x); m[39]=lrelu(a1.w+u1.y);
        u0 = upk(b2[4]); u1 = upk(b2[5]);
        m[40]=lrelu(a2.x+u0.x); m[41]=lrelu(a2.y+u0.y); m[42]=lrelu(a2.z+u1.x); m[43]=lrelu(a2.w+u1.y);
        u0 = upk(b2[6]); u1 = upk(b2[7]);
        m[44]=lrelu(a3.x+u0.x); m[45]=lrelu(a3.y+u0.y); m[46]=lrelu(a3.z+u1.x); m[47]=lrelu(a3.w+u1.y);
    }
    // warp segmented reduction (keys sorted within warp: CSR order)
#pragma unroll
    for (int delta = 1; delta < 32; delta <<= 1) {
        int rn = __shfl_down_sync(0xffffffffu, r, delta);
        bool take = (lane + delta < 32) && (rn == r);
#pragma unroll
        for (int j = 0; j < 48; j++) {
            float v = __shfl_down_sync(0xffffffffu, m[j], delta);
            if (take) m[j] += v;
        }
    }
    int rprev = __shfl_up_sync(0xffffffffu, r, 1);
    bool head = (lane == 0) || (rprev != r);
    if (head) {
        float* aggR = &g_aggR[(size_t)r * 32];
#pragma unroll
        for (int q = 0; q < 8; q++)
            red4(aggR + 4 * q, m[4*q], m[4*q+1], m[4*q+2], m[4*q+3]);
        float* aggS = &g_aggS[(size_t)r * 16];
#pragma unroll
        for (int q = 0; q < 4; q++)
            red4(aggS + 4 * q, m[32+4*q], m[33+4*q], m[34+4*q], m[35+4*q]);
    }
}

// ---- readout ----
__global__ void kOut(const float* __restrict__ W1, const float* __restrict__ b1,
                     const float* __restrict__ W2, const float* __restrict__ b2,
                     const int* __restrict__ batch, float* __restrict__ out) {
    __shared__ __align__(16) float sW1[48 * 144];
    __shared__ __align__(16) float sW2[144 * 6];
    __shared__ __align__(16) float sb1[144];
    __shared__ float sb2[6];
    for (int t = threadIdx.x; t < 48 * 144; t += blockDim.x) sW1[t] = W1[t];
    for (int t = threadIdx.x; t < 144 * 6; t += blockDim.x) sW2[t] = W2[t];
    for (int t = threadIdx.x; t < 144; t += blockDim.x) sb1[t] = b1[t];
    if (threadIdx.x < 6) sb2[threadIdx.x] = b2[threadIdx.x];
    __syncthreads();
    int n = blockIdx.x * blockDim.x + threadIdx.x;
    if (n >= NN) return;
    float invd = g_nacc[n * 4];
    float xc[48];
#pragma unroll
    for (int i = 0; i < 16; i++)
        xc[i] = g_xs[n * 16 + i] + g_aggS[n * 16 + i] * invd;
    float cc = g_ncs[2 * n], ss = g_ncs[2 * n + 1];
#pragma unroll
    for (int j = 0; j < 16; j++) {
        float gt = g_gate[n * 16 + j] * invd;
        float x0 = g_xrot[n * 32 + 2 * j]     + gt * g_aggR[n * 32 + 2 * j];
        float x1 = g_xrot[n * 32 + 2 * j + 1] + gt * g_aggR[n * 32 + 2 * j + 1];
        xc[16 + 2 * j]     = cc * x0 - ss * x1;
        xc[16 + 2 * j + 1] = ss * x0 + cc * x1;
    }
    float u[6];
#pragma unroll
    for (int q = 0; q < 6; q++) u[q] = sb2[q];
    for (int o = 0; o < 144; o += 4) {
        float4 h = *(const float4*)&sb1[o];
#pragma unroll
        for (int k = 0; k < 48; k++) {
            float4 w = *(const float4*)&sW1[k * 144 + o];
            float xv = xc[k];
            h.x = fmaf(xv, w.x, h.x);
            h.y = fmaf(xv, w.y, h.y);
            h.z = fmaf(xv, w.z, h.z);
            h.w = fmaf(xv, w.w, h.w);
        }
        h.x = lrelu(h.x); h.y = lrelu(h.y); h.z = lrelu(h.z); h.w = lrelu(h.w);
        float hv[4] = {h.x, h.y, h.z, h.w};
#pragma unroll
        for (int j = 0; j < 4; j++)
#pragma unroll
            for (int q = 0; q < 6; q++)
                u[q] = fmaf(hv[j], sW2[(o + j) * 6 + q], u[q]);
    }
    int b = batch[n];
#pragma unroll
    for (int q = 0; q < 6; q++) atomicAdd(&out[b * 6 + q], u[q]);
}

extern "C" void kernel_launch(void* const* d_in, const int* in_sizes, int n_in,
                              void* d_out, int out_size) {
    const float* pos   = (const float*)d_in[0];
    const float* Wemb  = (const float*)d_in[1];
    const float* wse   = (const float*)d_in[2];
    const float* bse   = (const float*)d_in[3];
    const float* Wg    = (const float*)d_in[4];
    const float* bg    = (const float*)d_in[5];
    const float* Wmix  = (const float*)d_in[6];
    const float* Wgate = (const float*)d_in[7];
    const float* bgate = (const float*)d_in[8];
    const float* Ws1   = (const float*)d_in[9];
    const float* bs1   = (const float*)d_in[10];
    const float* W1    = (const float*)d_in[11];
    const float* b1    = (const float*)d_in[12];
    const float* W2    = (const float*)d_in[13];
    const float* b2    = (const float*)d_in[14];
    const int*   ei    = (const int*)d_in[15];
    const int*   batch = (const int*)d_in[16];
    float* out = (float*)d_out;

    int nb = (NN + 255) / 256;
    int eb = (NE + 255) / 256;

    kZero<<<1563, 256>>>(out);
    kGraphAcc<<<nb, 256>>>(pos, batch);
    kCenter<<<nb, 256>>>(pos, batch);
    kDeg<<<eb, 256>>>(ei);
    kScanA<<<NBLK, 256>>>();
    kScanB<<<1, 512>>>();
    kScanC<<<NBLK, 256>>>();
    kEdgeFill<<<eb, 256>>>(ei);
    for (int l = 0; l < 3; l++) {
        kNodeFuse<<<nb, 256>>>(wse, bse, Wemb, Wmix, Wgate, bgate, Ws1, l);
        kEdgeLayer<<<eb, 256>>>(Wg, bg, Ws1, bs1, l);
    }
    kOut<<<(NN + 127) / 128, 128>>>(W1, b1, W2, b2, batch, out);
}